// round 8
// baseline (speedup 1.0000x reference)
#include <cuda_runtime.h>
#include <cuda_bf16.h>
#include <math.h>
#include <stdint.h>

#define B 2
#define S 2048
#define D 1024
#define H 16
#define DH 64
#define BS (B*S)     /* 4096 */
#define D3 (3*D)     /* 3072 */
#define NCH 8        /* key chunks */
#define CHK 256      /* keys per chunk */

// Scratch (allocation-free rule: __device__ globals)
__device__ float g_qkv[BS * D3];                 // 48 MB
__device__ float g_part[(size_t)NCH * BS * D];   // 128 MB
__device__ float g_lpart[(size_t)NCH * BS * H];  // 2 MB
__device__ float g_cost[S * 32];
__device__ float g_sint[S * 32];
__device__ __nv_bfloat16 g_xhi[BS * D],  g_xlo[BS * D];
__device__ __nv_bfloat16 g_wqT_hi[D3 * D], g_wqT_lo[D3 * D];
__device__ __nv_bfloat16 g_woT_hi[D * D],  g_woT_lo[D * D];
__device__ __nv_bfloat16 g_ahi[BS * D],  g_alo[BS * D];
__device__ __nv_bfloat16 g_sqh[BS * D], g_sql[BS * D];
__device__ __nv_bfloat16 g_skh[BS * D], g_skl[BS * D];
__device__ __nv_bfloat16 g_svh[BS * D], g_svl[BS * D];

// ============================================================================
// Helpers
// ============================================================================
__device__ __forceinline__ uint32_t smem_u32(const void* p) {
    uint32_t a;
    asm("{ .reg .u64 t; cvta.to.shared.u64 t, %1; cvt.u32.u64 %0, t; }"
        : "=r"(a) : "l"(p));
    return a;
}
__device__ __forceinline__ void bsplit(float v, __nv_bfloat16& h, __nv_bfloat16& l) {
    h = __float2bfloat16(v);
    l = __float2bfloat16(v - __bfloat162float(h));
}
__device__ __forceinline__ uint32_t packbf(float a, float b) {
    __nv_bfloat162 t = __floats2bfloat162_rn(a, b);
    return *(uint32_t*)&t;
}
__device__ __forceinline__ void cpa16(uint32_t s, const void* g) {
    uint64_t ga;
    asm("cvta.to.global.u64 %0, %1;" : "=l"(ga) : "l"(g));
    asm volatile("cp.async.cg.shared.global [%0], [%1], 16;"
                 :: "r"(s), "l"(ga) : "memory");
}
__device__ __forceinline__ void mma16(float* d, const uint32_t* a,
                                      uint32_t b0, uint32_t b1) {
    asm volatile(
        "mma.sync.aligned.m16n8k16.row.col.f32.bf16.bf16.f32 "
        "{%0,%1,%2,%3}, {%4,%5,%6,%7}, {%8,%9}, {%0,%1,%2,%3};"
        : "+f"(d[0]), "+f"(d[1]), "+f"(d[2]), "+f"(d[3])
        : "r"(a[0]), "r"(a[1]), "r"(a[2]), "r"(a[3]), "r"(b0), "r"(b1));
}
#define LDM4(r, addr) \
    asm volatile("ldmatrix.sync.aligned.m8n8.x4.shared.b16 {%0,%1,%2,%3}, [%4];" \
        : "=r"((r)[0]), "=r"((r)[1]), "=r"((r)[2]), "=r"((r)[3]) : "r"(addr))
#define LDM4T(r, addr) \
    asm volatile("ldmatrix.sync.aligned.m8n8.x4.trans.shared.b16 {%0,%1,%2,%3}, [%4];" \
        : "=r"((r)[0]), "=r"((r)[1]), "=r"((r)[2]), "=r"((r)[3]) : "r"(addr))

// ============================================================================
// Split kernels
// ============================================================================
__global__ void split_kernel(const float* __restrict__ src,
                             __nv_bfloat16* __restrict__ hi,
                             __nv_bfloat16* __restrict__ lo, int n4)
{
    int i = blockIdx.x * blockDim.x + threadIdx.x;
    if (i >= n4) return;
    float4 v = ((const float4*)src)[i];
    __nv_bfloat16 h0,h1,h2,h3,l0,l1,l2,l3;
    bsplit(v.x,h0,l0); bsplit(v.y,h1,l1); bsplit(v.z,h2,l2); bsplit(v.w,h3,l3);
    __nv_bfloat162 hp0, hp1, lp0, lp1;
    hp0.x=h0; hp0.y=h1; hp1.x=h2; hp1.y=h3;
    lp0.x=l0; lp0.y=l1; lp1.x=l2; lp1.y=l3;
    ((__nv_bfloat162*)hi)[2*i] = hp0; ((__nv_bfloat162*)hi)[2*i+1] = hp1;
    ((__nv_bfloat162*)lo)[2*i] = lp0; ((__nv_bfloat162*)lo)[2*i+1] = lp1;
}

__global__ void tsplit_kernel(const float* __restrict__ src,
                              __nv_bfloat16* __restrict__ dhi,
                              __nv_bfloat16* __restrict__ dlo, int R, int C)
{
    __shared__ float t[32][33];
    int c0 = blockIdx.x * 32, r0 = blockIdx.y * 32;
    int x = threadIdx.x, y = threadIdx.y;
    #pragma unroll
    for (int i = 0; i < 32; i += 8)
        t[y + i][x] = src[(size_t)(r0 + y + i) * C + c0 + x];
    __syncthreads();
    #pragma unroll
    for (int i = 0; i < 32; i += 8) {
        float v = t[x][y + i];
        __nv_bfloat16 h, l; bsplit(v, h, l);
        size_t o = (size_t)(c0 + y + i) * R + r0 + x;
        dhi[o] = h; dlo[o] = l;
    }
}

// ============================================================================
// 3xBF16 mma GEMM. CTA 128x128, BK=32, 512 threads = 16 warps (4x4),
// warp tile 32x32, 4-stage cp.async pipeline.
// ============================================================================
#define STG 40960
#define OFF_AHI 0
#define OFF_ALO 10240
#define OFF_BHI 20480
#define OFF_BLO 30720
#define GSMEM (4 * STG)

__global__ __launch_bounds__(512) void gemm_bf16x3_kernel(
    const __nv_bfloat16* __restrict__ Ahi, const __nv_bfloat16* __restrict__ Alo,
    const __nv_bfloat16* __restrict__ Bhi, const __nv_bfloat16* __restrict__ Blo,
    float* __restrict__ C, int M, int N, int K)
{
    extern __shared__ char smc[];
    const uint32_t sb = smem_u32(smc);
    const int tid = threadIdx.x, lane = tid & 31, wid = tid >> 5;
    const int wm = wid & 3, wn = wid >> 2;
    const int tg = lane & 3, gp = lane >> 2;
    const int m0 = blockIdx.y * 128, n0 = blockIdx.x * 128;
    const uint32_t lrow = ((lane & 7) + ((lane >> 3) & 1) * 8) * 80
                        + (lane >> 4) * 16;
    const int q  = tid & 3;
    const int r1 = tid >> 2;

    float acc[2][4][4];
    #pragma unroll
    for (int mi = 0; mi < 2; mi++)
        #pragma unroll
        for (int ni = 0; ni < 4; ni++)
            #pragma unroll
            for (int c = 0; c < 4; c++) acc[mi][ni][c] = 0.f;

    #define ISSUE(st, k0) {                                                     \
        uint32_t sba = sb + (st) * STG + r1 * 80 + q * 16;                      \
        size_t goA = (size_t)(m0 + r1) * K + (k0) + q * 8;                      \
        size_t goB = (size_t)(n0 + r1) * K + (k0) + q * 8;                      \
        cpa16(sba + OFF_AHI, Ahi + goA);                                        \
        cpa16(sba + OFF_ALO, Alo + goA);                                        \
        cpa16(sba + OFF_BHI, Bhi + goB);                                        \
        cpa16(sba + OFF_BLO, Blo + goB); }

    #define CMT asm volatile("cp.async.commit_group;" ::: "memory")

    ISSUE(0, 0);  CMT;
    ISSUE(1, 32); CMT;
    ISSUE(2, 64); CMT;

    const int nst = K / 32;
    for (int s = 0; s < nst; s++) {
        asm volatile("cp.async.wait_group 2;" ::: "memory");
        __syncthreads();
        if (s + 3 < nst) { ISSUE((s + 3) & 3, (s + 3) * 32); }
        CMT;

        const uint32_t sbase = sb + (s & 3) * STG;
        #pragma unroll
        for (int ks = 0; ks < 2; ks++) {
            uint32_t Ah[2][4], Al[2][4], Bh[2][4], Bl[2][4];
            const uint32_t kso = ks * 32 + lrow;
            #pragma unroll
            for (int mi = 0; mi < 2; mi++) {
                uint32_t ro = (wm * 32 + mi * 16) * 80 + kso;
                LDM4(Ah[mi], sbase + OFF_AHI + ro);
                LDM4(Al[mi], sbase + OFF_ALO + ro);
            }
            #pragma unroll
            for (int g = 0; g < 2; g++) {
                uint32_t ro = (wn * 32 + g * 16) * 80 + kso;
                LDM4(Bh[g], sbase + OFF_BHI + ro);
                LDM4(Bl[g], sbase + OFF_BLO + ro);
            }
            #pragma unroll
            for (int mi = 0; mi < 2; mi++)
                #pragma unroll
                for (int ni = 0; ni < 4; ni++) {
                    const int g = ni >> 1, sl = ni & 1;
                    float* dd = acc[mi][ni];
                    mma16(dd, Ah[mi], Bh[g][sl], Bh[g][sl + 2]);
                    mma16(dd, Ah[mi], Bl[g][sl], Bl[g][sl + 2]);
                    mma16(dd, Al[mi], Bh[g][sl], Bh[g][sl + 2]);
                }
        }
    }

    #pragma unroll
    for (int mi = 0; mi < 2; mi++) {
        int row = m0 + wm * 32 + mi * 16 + gp;
        #pragma unroll
        for (int ni = 0; ni < 4; ni++) {
            int col = n0 + wn * 32 + ni * 8 + 2 * tg;
            *(float2*)&C[(size_t)row * N + col] =
                make_float2(acc[mi][ni][0], acc[mi][ni][1]);
            *(float2*)&C[(size_t)(row + 8) * N + col] =
                make_float2(acc[mi][ni][2], acc[mi][ni][3]);
        }
    }
    #undef ISSUE
    #undef CMT
}

// ============================================================================
// RoPE tables (fp32)
// ============================================================================
__global__ void rope_table_kernel()
{
    int idx = blockIdx.x * blockDim.x + threadIdx.x;
    if (idx >= S * 32) return;
    int i = idx & 31;
    int s = idx >> 5;
    float inv = 1.0f / powf(10000.0f, (float)(2 * i) / 64.0f);
    float ang = (float)s * inv;
    float sn, c;
    sincosf(ang, &sn, &c);
    g_cost[idx] = c;
    g_sint[idx] = sn;
}

__global__ void rope_split_kernel(const float* __restrict__ qkv)
{
    int idx = blockIdx.x * blockDim.x + threadIdx.x;
    if (idx >= BS * H * 32) return;
    int i   = idx & 31;
    int h   = (idx >> 5) & (H - 1);
    int row = idx >> 9;
    int s   = row & (S - 1);
    int b   = row >> 11;

    float c  = g_cost[(s << 5) + i];
    float sn = g_sint[(s << 5) + i];

    size_t base = (size_t)row * D3 + h * DH + i;
    float q1 = qkv[base],         q2 = qkv[base + 32];
    float k1 = qkv[base + D],     k2 = qkv[base + D + 32];
    float v1 = qkv[base + 2*D],   v2 = qkv[base + 2*D + 32];

    float qr1 = q1 * c - q2 * sn, qr2 = q1 * sn + q2 * c;
    float kr1 = k1 * c - k2 * sn, kr2 = k1 * sn + k2 * c;

    size_t o = ((size_t)(b * H + h) * S + s) * 64 + i;
    __nv_bfloat16 hh, ll;
    bsplit(qr1, hh, ll); g_sqh[o] = hh;      g_sql[o] = ll;
    bsplit(qr2, hh, ll); g_sqh[o + 32] = hh; g_sql[o + 32] = ll;
    bsplit(kr1, hh, ll); g_skh[o] = hh;      g_skl[o] = ll;
    bsplit(kr2, hh, ll); g_skh[o + 32] = hh; g_skl[o + 32] = ll;
    bsplit(v1,  hh, ll); g_svh[o] = hh;      g_svl[o] = ll;
    bsplit(v2,  hh, ll); g_svh[o + 32] = hh; g_svl[o + 32] = ll;
}

// ============================================================================
// Tensor-core split-KV flash, CHK=256 keys per block as two double-buffered
// 128-key subtiles. Grid (qt=16, ch=8, bz=32), 256 threads = 8 warps.
// ============================================================================
#define FSTR 144
#define FT (128 * FSTR)   /* 18432 */
#define FOQH (0 * FT)
#define FOQL (1 * FT)
/* KV buffers: bi in {0,1} */
#define FOKH(bi) (2 * FT + (bi) * 4 * FT)
#define FOKL(bi) (3 * FT + (bi) * 4 * FT)
#define FOVH(bi) (4 * FT + (bi) * 4 * FT)
#define FOVL(bi) (5 * FT + (bi) * 4 * FT)
#define FOMSK (10 * FT)
#define FSMEM (10 * FT + 256)

struct FlashSub {
    float l0, l1;
};

__device__ __forceinline__ void flash_sub_compute(
    uint32_t sb, int bi, const uint32_t Qh[4][4], const uint32_t Ql[4][4],
    float accv[8][4], float& l0, float& l1,
    int j0, int qi0, bool causal, const char* smc_msk,
    int lane, int tg)
{
    const float scale = 0.125f;
    const uint32_t lrowA = ((lane & 7) + ((lane >> 3) & 1) * 8) * FSTR
                         + (lane >> 4) * 16;

    float acc[16][4];
    #pragma unroll
    for (int ni = 0; ni < 16; ni++)
        #pragma unroll
        for (int c = 0; c < 4; c++) acc[ni][c] = 0.f;

    #pragma unroll
    for (int g = 0; g < 8; g++) {
        #pragma unroll
        for (int ks = 0; ks < 4; ks++) {
            uint32_t Kh4[4], Kl4[4];
            uint32_t ro = (g * 16) * FSTR + ks * 32 + lrowA;
            LDM4(Kh4, sb + FOKH(bi) + ro);
            LDM4(Kl4, sb + FOKL(bi) + ro);
            #pragma unroll
            for (int sl = 0; sl < 2; sl++) {
                float* dd = acc[g * 2 + sl];
                mma16(dd, Qh[ks], Kh4[sl], Kh4[sl + 2]);
                mma16(dd, Qh[ks], Kl4[sl], Kl4[sl + 2]);
                mma16(dd, Ql[ks], Kh4[sl], Kh4[sl + 2]);
            }
        }
    }

    #pragma unroll
    for (int ni = 0; ni < 16; ni++) {
        #pragma unroll
        for (int e = 0; e < 2; e++) {
            int col = ni * 8 + 2 * tg + e;
            int colg = j0 + col;
            bool mv = causal ? true : (smc_msk[col] != 0);
            float p0 = (causal ? (colg <= qi0)     : mv)
                       ? __expf(acc[ni][e] * scale) : 0.f;
            float p1 = (causal ? (colg <= qi0 + 8) : mv)
                       ? __expf(acc[ni][e + 2] * scale) : 0.f;
            acc[ni][e] = p0; acc[ni][e + 2] = p1;
            l0 += p0; l1 += p1;
        }
    }

    #pragma unroll
    for (int kt = 0; kt < 8; kt++) {
        uint32_t Ph[4], Pl[4];
        #pragma unroll
        for (int half = 0; half < 2; half++) {
            const float* a = acc[2 * kt + half];
            #pragma unroll
            for (int rr = 0; rr < 2; rr++) {
                float pa = a[rr * 2], pb = a[rr * 2 + 1];
                __nv_bfloat16 ha = __float2bfloat16(pa);
                __nv_bfloat16 hb = __float2bfloat16(pb);
                float la = pa - __bfloat162float(ha);
                float lb = pb - __bfloat162float(hb);
                __nv_bfloat162 hp; hp.x = ha; hp.y = hb;
                Ph[half * 2 + rr] = *(uint32_t*)&hp;
                Pl[half * 2 + rr] = packbf(la, lb);
            }
        }
        #pragma unroll
        for (int g2 = 0; g2 < 4; g2++) {
            uint32_t Vh4[4], Vl4[4];
            uint32_t ro = (kt * 16 + (lane & 15)) * FSTR
                        + g2 * 32 + (lane >> 4) * 16;
            LDM4T(Vh4, sb + FOVH(bi) + ro);
            LDM4T(Vl4, sb + FOVL(bi) + ro);
            #pragma unroll
            for (int sl = 0; sl < 2; sl++) {
                float* dd = accv[g2 * 2 + sl];
                mma16(dd, Ph, Vh4[sl * 2], Vh4[sl * 2 + 1]);
                mma16(dd, Ph, Vl4[sl * 2], Vl4[sl * 2 + 1]);
                mma16(dd, Pl, Vh4[sl * 2], Vh4[sl * 2 + 1]);
            }
        }
    }
}

__global__ __launch_bounds__(256) void flash_mma_kernel(
    const unsigned char* __restrict__ mask, const int* __restrict__ is_causal_p)
{
    extern __shared__ char smc[];
    const uint32_t sb = smem_u32(smc);

    const int qt = blockIdx.x;
    const int ch = blockIdx.y;
    const int bz = blockIdx.z;
    const int b  = bz >> 4;
    const int h  = bz & (H - 1);
    const bool causal = (*is_causal_p) != 0;
    if (causal && 2 * ch > qt) return;

    const int tid = threadIdx.x, lane = tid & 31, wid = tid >> 5;
    const int tg = lane & 3, gp = lane >> 2;

    const size_t qb  = ((size_t)bz * S + qt * 128) * 64;
    const size_t kb0 = ((size_t)bz * S + ch * 256) * 64;

    // group 0: Q + KV subtile 0
    for (int t = tid; t < 1024; t += 256) {
        int r = t >> 3, c = t & 7;
        uint32_t dst = sb + r * FSTR + c * 16;
        size_t go = (size_t)r * 64 + c * 8;
        cpa16(dst + FOQH, g_sqh + qb + go);
        cpa16(dst + FOQL, g_sql + qb + go);
        cpa16(dst + FOKH(0), g_skh + kb0 + go);
        cpa16(dst + FOKL(0), g_skl + kb0 + go);
        cpa16(dst + FOVH(0), g_svh + kb0 + go);
        cpa16(dst + FOVL(0), g_svl + kb0 + go);
    }
    asm volatile("cp.async.commit_group;" ::: "memory");
    // group 1: KV subtile 1 (keys +128; always in-bounds)
    for (int t = tid; t < 1024; t += 256) {
        int r = t >> 3, c = t & 7;
        uint32_t dst = sb + r * FSTR + c * 16;
        size_t go = (size_t)(r + 128) * 64 + c * 8;
        cpa16(dst + FOKH(1), g_skh + kb0 + go);
        cpa16(dst + FOKL(1), g_skl + kb0 + go);
        cpa16(dst + FOVH(1), g_svh + kb0 + go);
        cpa16(dst + FOVL(1), g_svl + kb0 + go);
    }
    asm volatile("cp.async.commit_group;" ::: "memory");
    if (!causal)
        *(unsigned char*)(smc + FOMSK + tid) = mask[b * S + ch * 256 + tid];

    asm volatile("cp.async.wait_group 1;" ::: "memory");
    __syncthreads();

    const uint32_t lrowA = ((lane & 7) + ((lane >> 3) & 1) * 8) * FSTR
                         + (lane >> 4) * 16;
    uint32_t Qh[4][4], Ql[4][4];
    #pragma unroll
    for (int ks = 0; ks < 4; ks++) {
        uint32_t ro = (wid * 16) * FSTR + ks * 32 + lrowA;
        LDM4(Qh[ks], sb + FOQH + ro);
        LDM4(Ql[ks], sb + FOQL + ro);
    }

    const int qi0 = qt * 128 + wid * 16 + gp;
    float accv[8][4];
    #pragma unroll
    for (int ni = 0; ni < 8; ni++)
        #pragma unroll
        for (int c = 0; c < 4; c++) accv[ni][c] = 0.f;
    float l0 = 0.f, l1 = 0.f;

    flash_sub_compute(sb, 0, Qh, Ql, accv, l0, l1,
                      ch * 256, qi0, causal, smc + FOMSK, lane, tg);

    asm volatile("cp.async.wait_group 0;" ::: "memory");
    __syncthreads();

    const bool sub1 = causal ? (qt >= 2 * ch + 1) : true;
    if (sub1)
        flash_sub_compute(sb, 1, Qh, Ql, accv, l0, l1,
                          ch * 256 + 128, qi0, causal, smc + FOMSK + 128,
                          lane, tg);

    l0 += __shfl_xor_sync(0xFFFFFFFF, l0, 1);
    l0 += __shfl_xor_sync(0xFFFFFFFF, l0, 2);
    l1 += __shfl_xor_sync(0xFFFFFFFF, l1, 1);
    l1 += __shfl_xor_sync(0xFFFFFFFF, l1, 2);
    if (tg == 0) {
        g_lpart[((size_t)ch * BS + b * S + qi0)     * H + h] = l0;
        g_lpart[((size_t)ch * BS + b * S + qi0 + 8) * H + h] = l1;
    }

    float* p0 = g_part + ((size_t)ch * BS + b * S + qi0)     * D + h * DH;
    float* p1 = g_part + ((size_t)ch * BS + b * S + qi0 + 8) * D + h * DH;
    #pragma unroll
    for (int ni = 0; ni < 8; ni++) {
        int d = ni * 8 + 2 * tg;
        *(float2*)(p0 + d) = make_float2(accv[ni][0], accv[ni][1]);
        *(float2*)(p1 + d) = make_float2(accv[ni][2], accv[ni][3]);
    }
}

// ============================================================================
// Reduce partials -> attn as split bf16 (hi/lo)
// ============================================================================
__global__ void flash_reduce_kernel(const int* __restrict__ is_causal_p)
{
    int idx = blockIdx.x * blockDim.x + threadIdx.x;
    if (idx >= BS * D / 4) return;
    int base = idx * 4;
    int qrow = base / D;
    int d    = base % D;
    int h    = d >> 6;
    int q    = qrow & (S - 1);
    const int nv = (*is_causal_p) ? ((q >> 8) + 1) : NCH;

    float4 acc = make_float4(0.f, 0.f, 0.f, 0.f);
    float l = 0.f;
    for (int c = 0; c < nv; c++) {
        const float4 p = *(const float4*)(g_part + ((size_t)c * BS + qrow) * D + d);
        acc.x += p.x; acc.y += p.y; acc.z += p.z; acc.w += p.w;
        l += g_lpart[((size_t)c * BS + qrow) * H + h];
    }
    float inv = 1.f / l;
    float o0 = acc.x*inv, o1 = acc.y*inv, o2 = acc.z*inv, o3 = acc.w*inv;

    __nv_bfloat16 h0,h1,h2,h3,l0,l1,l2,l3;
    bsplit(o0,h0,l0); bsplit(o1,h1,l1); bsplit(o2,h2,l2); bsplit(o3,h3,l3);
    size_t o = (size_t)qrow * D + d;
    __nv_bfloat162 t;
    t.x=h0; t.y=h1; *(__nv_bfloat162*)(g_ahi + o)     = t;
    t.x=h2; t.y=h3; *(__nv_bfloat162*)(g_ahi + o + 2) = t;
    t.x=l0; t.y=l1; *(__nv_bfloat162*)(g_alo + o)     = t;
    t.x=l2; t.y=l3; *(__nv_bfloat162*)(g_alo + o + 2) = t;
}

// ============================================================================
extern "C" void kernel_launch(void* const* d_in, const int* in_sizes, int n_in,
                              void* d_out, int out_size)
{
    const float* x      = (const float*)d_in[0];
    const float* qkv_w  = (const float*)d_in[1];
    const float* out_w  = (const float*)d_in[2];
    const unsigned char* mask = (const unsigned char*)d_in[3];
    const int* is_causal = (const int*)d_in[4];
    float* out = (float*)d_out;

    float* qkv; cudaGetSymbolAddress((void**)&qkv, g_qkv);
    __nv_bfloat16 *xhi, *xlo, *wqh, *wql, *woh, *wol, *ahi, *alo;
    cudaGetSymbolAddress((void**)&xhi, g_xhi);
    cudaGetSymbolAddress((void**)&xlo, g_xlo);
    cudaGetSymbolAddress((void**)&wqh, g_wqT_hi);
    cudaGetSymbolAddress((void**)&wql, g_wqT_lo);
    cudaGetSymbolAddress((void**)&woh, g_woT_hi);
    cudaGetSymbolAddress((void**)&wol, g_woT_lo);
    cudaGetSymbolAddress((void**)&ahi, g_ahi);
    cudaGetSymbolAddress((void**)&alo, g_alo);

    cudaFuncSetAttribute(gemm_bf16x3_kernel,
                         cudaFuncAttributeMaxDynamicSharedMemorySize, GSMEM);
    cudaFuncSetAttribute(flash_mma_kernel,
                         cudaFuncAttributeMaxDynamicSharedMemorySize, FSMEM);

    // 0) Pre-splits + rope table
    split_kernel<<<(BS * D / 4 + 255) / 256, 256>>>(x, xhi, xlo, BS * D / 4);
    tsplit_kernel<<<dim3(D3 / 32, D / 32), dim3(32, 8)>>>(qkv_w, wqh, wql, D, D3);
    tsplit_kernel<<<dim3(D  / 32, D / 32), dim3(32, 8)>>>(out_w, woh, wol, D, D);
    rope_table_kernel<<<(S * 32 + 255) / 256, 256>>>();

    // 1) QKV projection
    gemm_bf16x3_kernel<<<dim3(D3 / 128, BS / 128), 512, GSMEM>>>(
        xhi, xlo, wqh, wql, qkv, BS, D3, D);

    // 2) RoPE + split q/k/v
    rope_split_kernel<<<(BS * H * 32 + 255) / 256, 256>>>(qkv);

    // 3) Flash (CHK=256 double-buffered) + reduce
    flash_mma_kernel<<<dim3(S / 128, NCH, B * H), 256, FSMEM>>>(mask, is_causal);
    flash_reduce_kernel<<<(BS * D / 4 + 255) / 256, 256>>>(is_causal);

    // 4) Output projection
    gemm_bf16x3_kernel<<<dim3(D / 128, BS / 128), 512, GSMEM>>>(
        ahi, alo, woh, wol, out, BS, D, D);
}

// round 10
// speedup vs baseline: 1.0423x; 1.0423x over previous
#include <cuda_runtime.h>
#include <cuda_bf16.h>
#include <math.h>
#include <stdint.h>

#define B 2
#define S 2048
#define D 1024
#define H 16
#define DH 64
#define BS (B*S)     /* 4096 */
#define D3 (3*D)     /* 3072 */
#define NCH 16       /* key chunks */
#define CHK 128      /* keys per chunk */

// Scratch (allocation-free rule: __device__ globals)
__device__ float g_part[(size_t)NCH * BS * D];   // 256 MB
__device__ float g_lpart[(size_t)NCH * BS * H];  // 4 MB
__device__ float g_cost[S * 32];
__device__ float g_sint[S * 32];
__device__ __nv_bfloat16 g_xhi[BS * D],  g_xlo[BS * D];
__device__ __nv_bfloat16 g_wqT_hi[D3 * D], g_wqT_lo[D3 * D];
__device__ __nv_bfloat16 g_woT_hi[D * D],  g_woT_lo[D * D];
__device__ __nv_bfloat16 g_ahi[BS * D],  g_alo[BS * D];
// roped q,k and v, split bf16, layout [b][h][s][64]
__device__ __nv_bfloat16 g_sqh[BS * D], g_sql[BS * D];
__device__ __nv_bfloat16 g_skh[BS * D], g_skl[BS * D];
__device__ __nv_bfloat16 g_svh[BS * D], g_svl[BS * D];

// ============================================================================
// Helpers
// ============================================================================
__device__ __forceinline__ uint32_t smem_u32(const void* p) {
    uint32_t a;
    asm("{ .reg .u64 t; cvta.to.shared.u64 t, %1; cvt.u32.u64 %0, t; }"
        : "=r"(a) : "l"(p));
    return a;
}
__device__ __forceinline__ void bsplit(float v, __nv_bfloat16& h, __nv_bfloat16& l) {
    h = __float2bfloat16(v);
    l = __float2bfloat16(v - __bfloat162float(h));
}
__device__ __forceinline__ uint32_t packbf(float a, float b) {
    __nv_bfloat162 t = __floats2bfloat162_rn(a, b);
    return *(uint32_t*)&t;
}
__device__ __forceinline__ void cpa16(uint32_t s, const void* g) {
    uint64_t ga;
    asm("cvta.to.global.u64 %0, %1;" : "=l"(ga) : "l"(g));
    asm volatile("cp.async.cg.shared.global [%0], [%1], 16;"
                 :: "r"(s), "l"(ga) : "memory");
}
__device__ __forceinline__ void mma16(float* d, const uint32_t* a,
                                      uint32_t b0, uint32_t b1) {
    asm volatile(
        "mma.sync.aligned.m16n8k16.row.col.f32.bf16.bf16.f32 "
        "{%0,%1,%2,%3}, {%4,%5,%6,%7}, {%8,%9}, {%0,%1,%2,%3};"
        : "+f"(d[0]), "+f"(d[1]), "+f"(d[2]), "+f"(d[3])
        : "r"(a[0]), "r"(a[1]), "r"(a[2]), "r"(a[3]), "r"(b0), "r"(b1));
}
#define LDM4(r, addr) \
    asm volatile("ldmatrix.sync.aligned.m8n8.x4.shared.b16 {%0,%1,%2,%3}, [%4];" \
        : "=r"((r)[0]), "=r"((r)[1]), "=r"((r)[2]), "=r"((r)[3]) : "r"(addr))
#define LDM4T(r, addr) \
    asm volatile("ldmatrix.sync.aligned.m8n8.x4.trans.shared.b16 {%0,%1,%2,%3}, [%4];" \
        : "=r"((r)[0]), "=r"((r)[1]), "=r"((r)[2]), "=r"((r)[3]) : "r"(addr))

// ============================================================================
// Split kernels
// ============================================================================
__global__ void split_kernel(const float* __restrict__ src,
                             __nv_bfloat16* __restrict__ hi,
                             __nv_bfloat16* __restrict__ lo, int n4)
{
    int i = blockIdx.x * blockDim.x + threadIdx.x;
    if (i >= n4) return;
    float4 v = ((const float4*)src)[i];
    __nv_bfloat16 h0,h1,h2,h3,l0,l1,l2,l3;
    bsplit(v.x,h0,l0); bsplit(v.y,h1,l1); bsplit(v.z,h2,l2); bsplit(v.w,h3,l3);
    __nv_bfloat162 hp0, hp1, lp0, lp1;
    hp0.x=h0; hp0.y=h1; hp1.x=h2; hp1.y=h3;
    lp0.x=l0; lp0.y=l1; lp1.x=l2; lp1.y=l3;
    ((__nv_bfloat162*)hi)[2*i] = hp0; ((__nv_bfloat162*)hi)[2*i+1] = hp1;
    ((__nv_bfloat162*)lo)[2*i] = lp0; ((__nv_bfloat162*)lo)[2*i+1] = lp1;
}

__global__ void tsplit_kernel(const float* __restrict__ src,
                              __nv_bfloat16* __restrict__ dhi,
                              __nv_bfloat16* __restrict__ dlo, int R, int C)
{
    __shared__ float t[32][33];
    int c0 = blockIdx.x * 32, r0 = blockIdx.y * 32;
    int x = threadIdx.x, y = threadIdx.y;
    #pragma unroll
    for (int i = 0; i < 32; i += 8)
        t[y + i][x] = src[(size_t)(r0 + y + i) * C + c0 + x];
    __syncthreads();
    #pragma unroll
    for (int i = 0; i < 32; i += 8) {
        float v = t[x][y + i];
        __nv_bfloat16 h, l; bsplit(v, h, l);
        size_t o = (size_t)(c0 + y + i) * R + r0 + x;
        dhi[o] = h; dlo[o] = l;
    }
}

// ============================================================================
// 3xBF16 mma GEMM. CTA 128x128, BK=32, 512 threads = 16 warps (4x4),
// warp tile 32x32, 3-stage cp.async (proven R7 config).
// mode 0: write fp32 C.  mode 1: fused rope+split epilogue for QKV.
// ============================================================================
#define STG 40960
#define OFF_AHI 0
#define OFF_ALO 10240
#define OFF_BHI 20480
#define OFF_BLO 30720
#define GSMEM (3 * STG)
#define STF 132   /* fp32 staging stride (floats) */

__global__ __launch_bounds__(512) void gemm_bf16x3_kernel(
    const __nv_bfloat16* __restrict__ Ahi, const __nv_bfloat16* __restrict__ Alo,
    const __nv_bfloat16* __restrict__ Bhi, const __nv_bfloat16* __restrict__ Blo,
    float* __restrict__ C, int M, int N, int K, int mode)
{
    extern __shared__ char smc[];
    const uint32_t sb = smem_u32(smc);
    const int tid = threadIdx.x, lane = tid & 31, wid = tid >> 5;
    const int wm = wid & 3, wn = wid >> 2;
    const int tg = lane & 3, gp = lane >> 2;
    const int m0 = blockIdx.y * 128, n0 = blockIdx.x * 128;
    const uint32_t lrow = ((lane & 7) + ((lane >> 3) & 1) * 8) * 80
                        + (lane >> 4) * 16;
    const int q  = tid & 3;
    const int r1 = tid >> 2;

    float acc[2][4][4];
    #pragma unroll
    for (int mi = 0; mi < 2; mi++)
        #pragma unroll
        for (int ni = 0; ni < 4; ni++)
            #pragma unroll
            for (int c = 0; c < 4; c++) acc[mi][ni][c] = 0.f;

    #define ISSUE(st, k0) {                                                     \
        uint32_t sba = sb + (st) * STG + r1 * 80 + q * 16;                      \
        size_t goA = (size_t)(m0 + r1) * K + (k0) + q * 8;                      \
        size_t goB = (size_t)(n0 + r1) * K + (k0) + q * 8;                      \
        cpa16(sba + OFF_AHI, Ahi + goA);                                        \
        cpa16(sba + OFF_ALO, Alo + goA);                                        \
        cpa16(sba + OFF_BHI, Bhi + goB);                                        \
        cpa16(sba + OFF_BLO, Blo + goB); }

    #define CMT asm volatile("cp.async.commit_group;" ::: "memory")

    ISSUE(0, 0);  CMT;
    ISSUE(1, 32); CMT;

    const int nst = K / 32;
    for (int s = 0; s < nst; s++) {
        asm volatile("cp.async.wait_group 1;" ::: "memory");
        __syncthreads();
        if (s + 2 < nst) { ISSUE((s + 2) % 3, (s + 2) * 32); }
        CMT;

        const uint32_t sbase = sb + (s % 3) * STG;
        #pragma unroll
        for (int ks = 0; ks < 2; ks++) {
            uint32_t Ah[2][4], Al[2][4], Bh[2][4], Bl[2][4];
            const uint32_t kso = ks * 32 + lrow;
            #pragma unroll
            for (int mi = 0; mi < 2; mi++) {
                uint32_t ro = (wm * 32 + mi * 16) * 80 + kso;
                LDM4(Ah[mi], sbase + OFF_AHI + ro);
                LDM4(Al[mi], sbase + OFF_ALO + ro);
            }
            #pragma unroll
            for (int g = 0; g < 2; g++) {
                uint32_t ro = (wn * 32 + g * 16) * 80 + kso;
                LDM4(Bh[g], sbase + OFF_BHI + ro);
                LDM4(Bl[g], sbase + OFF_BLO + ro);
            }
            #pragma unroll
            for (int mi = 0; mi < 2; mi++)
                #pragma unroll
                for (int ni = 0; ni < 4; ni++) {
                    const int g = ni >> 1, sl = ni & 1;
                    float* dd = acc[mi][ni];
                    mma16(dd, Ah[mi], Bh[g][sl], Bh[g][sl + 2]);
                    mma16(dd, Ah[mi], Bl[g][sl], Bl[g][sl + 2]);
                    mma16(dd, Al[mi], Bh[g][sl], Bh[g][sl + 2]);
                }
        }
    }

    if (mode == 0) {
        #pragma unroll
        for (int mi = 0; mi < 2; mi++) {
            int row = m0 + wm * 32 + mi * 16 + gp;
            #pragma unroll
            for (int ni = 0; ni < 4; ni++) {
                int col = n0 + wn * 32 + ni * 8 + 2 * tg;
                *(float2*)&C[(size_t)row * N + col] =
                    make_float2(acc[mi][ni][0], acc[mi][ni][1]);
                *(float2*)&C[(size_t)(row + 8) * N + col] =
                    make_float2(acc[mi][ni][2], acc[mi][ni][3]);
            }
        }
    } else {
        // Fused rope + hi/lo split epilogue for the QKV projection.
        // Stage the 128x128 fp32 tile in (now idle) pipeline smem.
        __syncthreads();
        float* st = (float*)smc;
        #pragma unroll
        for (int mi = 0; mi < 2; mi++) {
            int row = wm * 32 + mi * 16 + gp;
            #pragma unroll
            for (int ni = 0; ni < 4; ni++) {
                int col = wn * 32 + ni * 8 + 2 * tg;
                *(float2*)&st[row * STF + col] =
                    make_float2(acc[mi][ni][0], acc[mi][ni][1]);
                *(float2*)&st[(row + 8) * STF + col] =
                    make_float2(acc[mi][ni][2], acc[mi][ni][3]);
            }
        }
        __syncthreads();

        // 128 rows x 2 heads x 32 pairs = 8192 work items
        for (int e = tid; e < 8192; e += 512) {
            int row  = e >> 6;
            int hcol = (e >> 5) & 1;
            int i    = e & 31;
            int grow = m0 + row;
            int s    = grow & (S - 1);
            int b    = grow >> 11;
            int gcol = n0 + hcol * 64;
            int region = gcol >> 10;            // 0=q 1=k 2=v
            int hh     = (gcol & 1023) >> 6;    // head

            float v1 = st[row * STF + hcol * 64 + i];
            float v2 = st[row * STF + hcol * 64 + i + 32];
            size_t o = ((size_t)(b * H + hh) * S + s) * 64 + i;
            __nv_bfloat16 ph, pl;

            if (region == 2) {
                bsplit(v1, ph, pl); g_svh[o] = ph;      g_svl[o] = pl;
                bsplit(v2, ph, pl); g_svh[o + 32] = ph; g_svl[o + 32] = pl;
            } else {
                float c  = g_cost[(s << 5) + i];
                float sn = g_sint[(s << 5) + i];
                float r1 = v1 * c - v2 * sn;
                float r2 = v1 * sn + v2 * c;
                if (region == 0) {
                    bsplit(r1, ph, pl); g_sqh[o] = ph;      g_sql[o] = pl;
                    bsplit(r2, ph, pl); g_sqh[o + 32] = ph; g_sql[o + 32] = pl;
                } else {
                    bsplit(r1, ph, pl); g_skh[o] = ph;      g_skl[o] = pl;
                    bsplit(r2, ph, pl); g_skh[o + 32] = ph; g_skl[o + 32] = pl;
                }
            }
        }
    }
    #undef ISSUE
    #undef CMT
}

// ============================================================================
// RoPE tables (fp32)
// ============================================================================
__global__ void rope_table_kernel()
{
    int idx = blockIdx.x * blockDim.x + threadIdx.x;
    if (idx >= S * 32) return;
    int i = idx & 31;
    int s = idx >> 5;
    float inv = 1.0f / powf(10000.0f, (float)(2 * i) / 64.0f);
    float ang = (float)s * inv;
    float sn, c;
    sincosf(ang, &sn, &c);
    g_cost[idx] = c;
    g_sint[idx] = sn;
}

// ============================================================================
// Tensor-core split-KV flash (proven R7 config: CHK=128, single KV buffer).
// ============================================================================
#define FSTR 144
#define FT (128 * FSTR)
#define FOQH (0 * FT)
#define FOQL (1 * FT)
#define FOKH (2 * FT)
#define FOKL (3 * FT)
#define FOVH (4 * FT)
#define FOVL (5 * FT)
#define FOMSK (6 * FT)
#define FSMEM (6 * FT + 128)

__global__ __launch_bounds__(256) void flash_mma_kernel(
    const unsigned char* __restrict__ mask, const int* __restrict__ is_causal_p)
{
    extern __shared__ char smc[];
    const uint32_t sb = smem_u32(smc);

    const int qt = blockIdx.x;
    const int ch = blockIdx.y;
    const int bz = blockIdx.z;
    const int b  = bz >> 4;
    const int h  = bz & (H - 1);
    const bool causal = (*is_causal_p) != 0;
    if (causal && ch > qt) return;

    const int tid = threadIdx.x, lane = tid & 31, wid = tid >> 5;
    const int tg = lane & 3, gp = lane >> 2;
    const float scale = 0.125f;

    const size_t qb = ((size_t)bz * S + qt * 128) * 64;
    const size_t kb = ((size_t)bz * S + ch * 128) * 64;
    for (int t = tid; t < 1024; t += 256) {
        int r = t >> 3, c = t & 7;
        uint32_t dst = sb + r * FSTR + c * 16;
        size_t go = (size_t)r * 64 + c * 8;
        cpa16(dst + FOQH, g_sqh + qb + go);
        cpa16(dst + FOQL, g_sql + qb + go);
        cpa16(dst + FOKH, g_skh + kb + go);
        cpa16(dst + FOKL, g_skl + kb + go);
        cpa16(dst + FOVH, g_svh + kb + go);
        cpa16(dst + FOVL, g_svl + kb + go);
    }
    asm volatile("cp.async.commit_group;" ::: "memory");
    if (!causal && tid < 128)
        *(unsigned char*)(smc + FOMSK + tid) = mask[b * S + ch * 128 + tid];
    asm volatile("cp.async.wait_group 0;" ::: "memory");
    __syncthreads();

    const uint32_t lrowA = ((lane & 7) + ((lane >> 3) & 1) * 8) * FSTR
                         + (lane >> 4) * 16;

    uint32_t Qh[4][4], Ql[4][4];
    #pragma unroll
    for (int ks = 0; ks < 4; ks++) {
        uint32_t ro = (wid * 16) * FSTR + ks * 32 + lrowA;
        LDM4(Qh[ks], sb + FOQH + ro);
        LDM4(Ql[ks], sb + FOQL + ro);
    }

    float acc[16][4];
    #pragma unroll
    for (int ni = 0; ni < 16; ni++)
        #pragma unroll
        for (int c = 0; c < 4; c++) acc[ni][c] = 0.f;

    #pragma unroll
    for (int g = 0; g < 8; g++) {
        #pragma unroll
        for (int ks = 0; ks < 4; ks++) {
            uint32_t Kh4[4], Kl4[4];
            uint32_t ro = (g * 16) * FSTR + ks * 32 + lrowA;
            LDM4(Kh4, sb + FOKH + ro);
            LDM4(Kl4, sb + FOKL + ro);
            #pragma unroll
            for (int sl = 0; sl < 2; sl++) {
                float* dd = acc[g * 2 + sl];
                mma16(dd, Qh[ks], Kh4[sl], Kh4[sl + 2]);
                mma16(dd, Qh[ks], Kl4[sl], Kl4[sl + 2]);
                mma16(dd, Ql[ks], Kh4[sl], Kh4[sl + 2]);
            }
        }
    }

    const int qi0 = qt * 128 + wid * 16 + gp;
    float l0 = 0.f, l1 = 0.f;
    #pragma unroll
    for (int ni = 0; ni < 16; ni++) {
        #pragma unroll
        for (int e = 0; e < 2; e++) {
            int colg = ch * 128 + ni * 8 + 2 * tg + e;
            bool mv = causal ? true
                             : (*(unsigned char*)(smc + FOMSK + ni*8 + 2*tg + e) != 0);
            float p0 = (causal ? (colg <= qi0)     : mv)
                       ? __expf(acc[ni][e] * scale) : 0.f;
            float p1 = (causal ? (colg <= qi0 + 8) : mv)
                       ? __expf(acc[ni][e + 2] * scale) : 0.f;
            acc[ni][e] = p0; acc[ni][e + 2] = p1;
            l0 += p0; l1 += p1;
        }
    }
    l0 += __shfl_xor_sync(0xFFFFFFFF, l0, 1);
    l0 += __shfl_xor_sync(0xFFFFFFFF, l0, 2);
    l1 += __shfl_xor_sync(0xFFFFFFFF, l1, 1);
    l1 += __shfl_xor_sync(0xFFFFFFFF, l1, 2);
    if (tg == 0) {
        g_lpart[((size_t)ch * BS + b * S + qi0)     * H + h] = l0;
        g_lpart[((size_t)ch * BS + b * S + qi0 + 8) * H + h] = l1;
    }

    float accv[8][4];
    #pragma unroll
    for (int ni = 0; ni < 8; ni++)
        #pragma unroll
        for (int c = 0; c < 4; c++) accv[ni][c] = 0.f;

    #pragma unroll
    for (int kt = 0; kt < 8; kt++) {
        uint32_t Ph[4], Pl[4];
        #pragma unroll
        for (int half = 0; half < 2; half++) {
            const float* a = acc[2 * kt + half];
            #pragma unroll
            for (int rr = 0; rr < 2; rr++) {
                float pa = a[rr * 2], pb = a[rr * 2 + 1];
                __nv_bfloat16 ha = __float2bfloat16(pa);
                __nv_bfloat16 hb = __float2bfloat16(pb);
                float la = pa - __bfloat162float(ha);
                float lb = pb - __bfloat162float(hb);
                __nv_bfloat162 hp; hp.x = ha; hp.y = hb;
                Ph[half * 2 + rr] = *(uint32_t*)&hp;
                Pl[half * 2 + rr] = packbf(la, lb);
            }
        }
        #pragma unroll
        for (int g2 = 0; g2 < 4; g2++) {
            uint32_t Vh4[4], Vl4[4];
            uint32_t ro = (kt * 16 + (lane & 15)) * FSTR
                        + g2 * 32 + (lane >> 4) * 16;
            LDM4T(Vh4, sb + FOVH + ro);
            LDM4T(Vl4, sb + FOVL + ro);
            #pragma unroll
            for (int sl = 0; sl < 2; sl++) {
                float* dd = accv[g2 * 2 + sl];
                mma16(dd, Ph, Vh4[sl * 2], Vh4[sl * 2 + 1]);
                mma16(dd, Ph, Vl4[sl * 2], Vl4[sl * 2 + 1]);
                mma16(dd, Pl, Vh4[sl * 2], Vh4[sl * 2 + 1]);
            }
        }
    }

    float* p0 = g_part + ((size_t)ch * BS + b * S + qi0)     * D + h * DH;
    float* p1 = g_part + ((size_t)ch * BS + b * S + qi0 + 8) * D + h * DH;
    #pragma unroll
    for (int ni = 0; ni < 8; ni++) {
        int d = ni * 8 + 2 * tg;
        *(float2*)(p0 + d) = make_float2(accv[ni][0], accv[ni][1]);
        *(float2*)(p1 + d) = make_float2(accv[ni][2], accv[ni][3]);
    }
}

// ============================================================================
// Reduce partials -> attn as split bf16 (hi/lo)
// ============================================================================
__global__ void flash_reduce_kernel(const int* __restrict__ is_causal_p)
{
    int idx = blockIdx.x * blockDim.x + threadIdx.x;
    if (idx >= BS * D / 4) return;
    int base = idx * 4;
    int qrow = base / D;
    int d    = base % D;
    int h    = d >> 6;
    int q    = qrow & (S - 1);
    const int nv = (*is_causal_p) ? ((q >> 7) + 1) : NCH;

    float4 acc = make_float4(0.f, 0.f, 0.f, 0.f);
    float l = 0.f;
    for (int c = 0; c < nv; c++) {
        const float4 p = *(const float4*)(g_part + ((size_t)c * BS + qrow) * D + d);
        acc.x += p.x; acc.y += p.y; acc.z += p.z; acc.w += p.w;
        l += g_lpart[((size_t)c * BS + qrow) * H + h];
    }
    float inv = 1.f / l;
    float o0 = acc.x*inv, o1 = acc.y*inv, o2 = acc.z*inv, o3 = acc.w*inv;

    __nv_bfloat16 h0,h1,h2,h3,l0,l1,l2,l3;
    bsplit(o0,h0,l0); bsplit(o1,h1,l1); bsplit(o2,h2,l2); bsplit(o3,h3,l3);
    size_t o = (size_t)qrow * D + d;
    __nv_bfloat162 t;
    t.x=h0; t.y=h1; *(__nv_bfloat162*)(g_ahi + o)     = t;
    t.x=h2; t.y=h3; *(__nv_bfloat162*)(g_ahi + o + 2) = t;
    t.x=l0; t.y=l1; *(__nv_bfloat162*)(g_alo + o)     = t;
    t.x=l2; t.y=l3; *(__nv_bfloat162*)(g_alo + o + 2) = t;
}

// ============================================================================
extern "C" void kernel_launch(void* const* d_in, const int* in_sizes, int n_in,
                              void* d_out, int out_size)
{
    const float* x      = (const float*)d_in[0];
    const float* qkv_w  = (const float*)d_in[1];
    const float* out_w  = (const float*)d_in[2];
    const unsigned char* mask = (const unsigned char*)d_in[3];
    const int* is_causal = (const int*)d_in[4];
    float* out = (float*)d_out;

    __nv_bfloat16 *xhi, *xlo, *wqh, *wql, *woh, *wol, *ahi, *alo;
    cudaGetSymbolAddress((void**)&xhi, g_xhi);
    cudaGetSymbolAddress((void**)&xlo, g_xlo);
    cudaGetSymbolAddress((void**)&wqh, g_wqT_hi);
    cudaGetSymbolAddress((void**)&wql, g_wqT_lo);
    cudaGetSymbolAddress((void**)&woh, g_woT_hi);
    cudaGetSymbolAddress((void**)&wol, g_woT_lo);
    cudaGetSymbolAddress((void**)&ahi, g_ahi);
    cudaGetSymbolAddress((void**)&alo, g_alo);

    cudaFuncSetAttribute(gemm_bf16x3_kernel,
                         cudaFuncAttributeMaxDynamicSharedMemorySize, GSMEM);
    cudaFuncSetAttribute(flash_mma_kernel,
                         cudaFuncAttributeMaxDynamicSharedMemorySize, FSMEM);

    // 0) Pre-splits + rope table (table must precede the fused QKV epilogue)
    split_kernel<<<(BS * D / 4 + 255) / 256, 256>>>(x, xhi, xlo, BS * D / 4);
    tsplit_kernel<<<dim3(D3 / 32, D / 32), dim3(32, 8)>>>(qkv_w, wqh, wql, D, D3);
    tsplit_kernel<<<dim3(D  / 32, D / 32), dim3(32, 8)>>>(out_w, woh, wol, D, D);
    rope_table_kernel<<<(S * 32 + 255) / 256, 256>>>();

    // 1) QKV projection with fused rope+split epilogue (mode 1)
    gemm_bf16x3_kernel<<<dim3(D3 / 128, BS / 128), 512, GSMEM>>>(
        xhi, xlo, wqh, wql, nullptr, BS, D3, D, 1);

    // 2) Flash (CHK=128) + reduce
    flash_mma_kernel<<<dim3(S / 128, NCH, B * H), 256, FSMEM>>>(mask, is_causal);
    flash_reduce_kernel<<<(BS * D / 4 + 255) / 256, 256>>>(is_causal);

    // 3) Output projection (mode 0)
    gemm_bf16x3_kernel<<<dim3(D / 128, BS / 128), 512, GSMEM>>>(
        ahi, alo, woh, wol, out, BS, D, D, 0);
}